// round 14
// baseline (speedup 1.0000x reference)
#include <cuda_runtime.h>
#include <cuda_bf16.h>
#include <cstdint>
#include <math.h>

// Problem constants (fixed by reference)
#define BB 256
#define PP 16
#define LL 4
#define EE 128
#define NPAIR 4096
#define NNODE 512
#define C1 512
#define C2 256
#define LIST_CAP 64
#define XSTRH 136            // X row stride in bf16 units (272B) -> conflict-free B frags

typedef unsigned long long ull;
typedef unsigned short ushort_t;

// ---------------- device scratch (no allocations allowed) ----------------
__device__ float g_bufA[NPAIR * 2 * EE];   // 4 MB ping
__device__ float g_bufB[NPAIR * 2 * EE];   // 4 MB pong
__device__ float g_pooledT[2 * EE * BB];
__device__ float g_h1T[C1 * BB];
__device__ float g_h2T[C2 * BB];
__device__ int   g_meta[LL * NNODE];
__device__ int   g_list[LL * NNODE * LIST_CAP];

// ---------------- helpers ----------------
__device__ __forceinline__ void fma2(ull& d, ull a, ull b) {
    asm("fma.rn.f32x2 %0, %1, %2, %0;" : "+l"(d) : "l"(a), "l"(b));
}
__device__ __forceinline__ ull pack2(float x) {
    ull r; unsigned u = __float_as_uint(x);
    asm("mov.b64 %0, {%1, %2};" : "=l"(r) : "r"(u), "r"(u));
    return r;
}
// pack two floats into bf16x2 (x0 -> low half, x1 -> high half)
__device__ __forceinline__ uint32_t cvt_bf16x2(float x0, float x1) {
    uint32_t r;
    asm("cvt.rn.bf16x2.f32 %0, %1, %2;" : "=r"(r) : "f"(x1), "f"(x0));
    return r;
}
// given float2 (x0,x1): produce hi-pack and lo-pack (residual) bf16x2
__device__ __forceinline__ void split2(float x0, float x1, uint32_t& hi, uint32_t& lo) {
    hi = cvt_bf16x2(x0, x1);
    float h0 = __uint_as_float(hi << 16);
    float h1 = __uint_as_float(hi & 0xffff0000u);
    lo = cvt_bf16x2(x0 - h0, x1 - h1);
}
__device__ __forceinline__ void mma16816(float* c, uint32_t a0, uint32_t a1, uint32_t a2, uint32_t a3,
                                         uint32_t b0, uint32_t b1) {
    asm volatile(
        "mma.sync.aligned.m16n8k16.row.col.f32.bf16.bf16.f32 "
        "{%0,%1,%2,%3}, {%4,%5,%6,%7}, {%8,%9}, {%0,%1,%2,%3};"
        : "+f"(c[0]), "+f"(c[1]), "+f"(c[2]), "+f"(c[3])
        : "r"(a0), "r"(a1), "r"(a2), "r"(a3), "r"(b0), "r"(b1));
}

// ---------------- list building ----------------
__global__ void build_lists_kernel(const int* __restrict__ mids)
{
    int idx = blockIdx.x * 256 + threadIdx.x;
    if (idx >= NPAIR * LL) return;
    int p = idx >> 2, l = idx & 3;
    int node = mids[p * LL + l];
    int pos = atomicAdd(&g_meta[l * NNODE + node], 1);
    if (pos < LIST_CAP)
        g_list[(l * NNODE + node) * LIST_CAP + pos] = p;
}

// ---------------- layer kernel: one block per (node, chunk-slot) ----------------
// grid.x = NNODE*4 (chunk slots of 16 pairs); empty slots exit immediately.
// 256 threads = 8 warps; warp w computes rows [w*16, w*16+16) x 32 vectors.
// W loaded fp32 from the input tensor (fragment pattern), split to bf16 hi/lo in
// registers; each W element read ONCE per block, reused by all 3 split-products.
template <bool FIRST>
__global__ __launch_bounds__(256, 4) void layer_mma_kernel(
    int layer, const float* __restrict__ Wg, const float* __restrict__ bias,
    const int* __restrict__ sids, const int* __restrict__ eids,
    const float* __restrict__ embed,
    const float* __restrict__ bufIn, float* __restrict__ bufOut)
{
    const int node = blockIdx.x >> 2;
    const int c0   = (blockIdx.x & 3) << 4;
    int kp = g_meta[layer * NNODE + node];
    kp = kp < LIST_CAP ? kp : LIST_CAP;
    if (c0 >= kp) return;
    const int nv = 2 * min(16, kp - c0);
    const int* lst = &g_list[(layer * NNODE + node) * LIST_CAP + c0];

    __shared__ ushort_t sxh[32 * XSTRH];
    __shared__ ushort_t sxl[32 * XSTRH];

    const int tid = threadIdx.x, lane = tid & 31, w = tid >> 5;

    // ---- gather X, split into bf16 hi/lo tiles (vectors >= nv stale; discarded) ----
    for (int f = tid; f < nv * 32; f += 256) {
        int v = f >> 5, i4 = f & 31;
        int pr = lst[v >> 1];
        const float4* src;
        if (FIRST) {
            int id = (v & 1) ? eids[pr] : sids[pr];
            src = (const float4*)(embed + (size_t)id * EE);
        } else {
            src = (const float4*)(bufIn + ((size_t)pr * 2 + (v & 1)) * EE);
        }
        float4 x = src[i4];
        uint32_t h01, l01, h23, l23;
        split2(x.x, x.y, h01, l01);
        split2(x.z, x.w, h23, l23);
        int o = v * XSTRH + i4 * 4;
        *(uint2*)&sxh[o] = make_uint2(h01, h23);
        *(uint2*)&sxl[o] = make_uint2(l01, l23);
    }
    __syncthreads();

    // ---- 3-product bf16-split mma: Whi*Xhi + Whi*Xlo + Wlo*Xhi ----
    float c[4][4];
    #pragma unroll
    for (int nt = 0; nt < 4; ++nt)
        #pragma unroll
        for (int q = 0; q < 4; ++q) c[nt][q] = 0.f;

    const float* Wn = Wg + (size_t)node * EE * EE;
    const int rbase = w * 16 + (lane >> 2);    // A frag row (q adds 8)
    const int kbase = (lane & 3) << 1;         // A/B frag k pair base
    const int brow = lane >> 2;                // B frag: n offset within ntile

    #pragma unroll 2
    for (int s = 0; s < 8; ++s) {
        const int ks = s * 16 + kbase;
        // this warp's fp32 W fragment (each element exactly once)
        uint32_t ahi[4], alo[4];
        {
            const float* wr0 = Wn + (size_t)rbase * EE + ks;
            const float* wr1 = wr0 + 8 * EE;
            float2 w00 = *(const float2*)wr0;          // (r,   k..k+1)
            float2 w10 = *(const float2*)wr1;          // (r+8, k..k+1)
            float2 w01 = *(const float2*)(wr0 + 8);    // (r,   k+8..k+9)
            float2 w11 = *(const float2*)(wr1 + 8);    // (r+8, k+8..k+9)
            split2(w00.x, w00.y, ahi[0], alo[0]);
            split2(w10.x, w10.y, ahi[1], alo[1]);
            split2(w01.x, w01.y, ahi[2], alo[2]);
            split2(w11.x, w11.y, ahi[3], alo[3]);
        }
        #pragma unroll
        for (int nt = 0; nt < 4; ++nt) {
            const int xo = (nt * 8 + brow) * XSTRH + s * 16 + kbase;
            uint32_t bh0 = *(const uint32_t*)&sxh[xo];
            uint32_t bh1 = *(const uint32_t*)&sxh[xo + 8];
            uint32_t bl0 = *(const uint32_t*)&sxl[xo];
            uint32_t bl1 = *(const uint32_t*)&sxl[xo + 8];
            mma16816(c[nt], ahi[0], ahi[1], ahi[2], ahi[3], bh0, bh1);
            mma16816(c[nt], ahi[0], ahi[1], ahi[2], ahi[3], bl0, bl1);
            mma16816(c[nt], alo[0], alo[1], alo[2], alo[3], bh0, bh1);
        }
    }

    // ---- epilogue: +bias, guarded scatter ----
    const int r0 = w * 16 + (lane >> 2);
    const float bv0 = bias[node * EE + r0];
    const float bv1 = bias[node * EE + r0 + 8];
    #pragma unroll
    for (int nt = 0; nt < 4; ++nt) {
        int v0 = nt * 8 + ((lane & 3) << 1);
        int v1 = v0 + 1;
        if (v0 < nv) {
            int pr = lst[v0 >> 1];
            float* dst = bufOut + ((size_t)pr * 2 + (v0 & 1)) * EE;
            dst[r0]     = c[nt][0] + bv0;
            dst[r0 + 8] = c[nt][2] + bv1;
        }
        if (v1 < nv) {
            int pr = lst[v1 >> 1];
            float* dst = bufOut + ((size_t)pr * 2 + (v1 & 1)) * EE;
            dst[r0]     = c[nt][1] + bv0;
            dst[r0 + 8] = c[nt][3] + bv1;
        }
    }
}

// ---------------- pooling: pooledT[f][b] ----------------
__global__ void pool_kernel(const float* __restrict__ buf,
                            const int* __restrict__ counts,
                            float* __restrict__ pooledT)
{
    const int b = blockIdx.x;
    const int f = threadIdx.x;
    const int half = f >> 7, fi = f & 127;
    float acc = 0.f, cs = 0.f;
    #pragma unroll
    for (int p = 0; p < PP; ++p) {
        float c = (float)counts[b * PP + p];
        acc += c * buf[((size_t)((b * PP + p) * 2 + half)) * EE + fi];
        cs += c;
    }
    pooledT[(size_t)f * BB + b] = acc / cs;
}

// ---------------- MLP layer (relu): yT[j][b] ----------------
template <int IN>
__global__ void mlp_kernel(const float* __restrict__ Wm, const float* __restrict__ bm,
                           const float* __restrict__ xT, float* __restrict__ yT)
{
    __shared__ float wt[IN * 8];
    const int jt = blockIdx.x * 8;
    const int t = threadIdx.x;
    for (int f = t; f < IN * 8; f += 256) {
        int jj = f / IN, i = f % IN;
        wt[i * 8 + jj] = Wm[(size_t)(jt + jj) * IN + i];
    }
    __syncthreads();

    ull acc[4] = {0ull, 0ull, 0ull, 0ull};
    #pragma unroll 8
    for (int i = 0; i < IN; ++i) {
        ull pp = pack2(xT[(size_t)i * BB + t]);
        ulonglong2 wa = *(ulonglong2*)&wt[i * 8];
        ulonglong2 wb = *(ulonglong2*)&wt[i * 8 + 4];
        fma2(acc[0], wa.x, pp);
        fma2(acc[1], wa.y, pp);
        fma2(acc[2], wb.x, pp);
        fma2(acc[3], wb.y, pp);
    }
    #pragma unroll
    for (int q = 0; q < 4; ++q) {
        int j0 = jt + 2 * q, j1 = j0 + 1;
        float v0 = __uint_as_float((unsigned)acc[q]) + bm[j0];
        float v1 = __uint_as_float((unsigned)(acc[q] >> 32)) + bm[j1];
        yT[(size_t)j0 * BB + t] = fmaxf(v0, 0.f);
        yT[(size_t)j1 * BB + t] = fmaxf(v1, 0.f);
    }
}

// ---------------- final ----------------
__global__ void out_kernel(const float* __restrict__ W3, const float* __restrict__ b3,
                           const float* __restrict__ h2T, float* __restrict__ out)
{
    const int t = threadIdx.x;
    float acc = 0.f;
    #pragma unroll 8
    for (int j = 0; j < C2; ++j)
        acc += W3[j] * h2T[(size_t)j * BB + t];
    acc += b3[0];
    out[t] = 1.f / (1.f + expf(-acc));
}

// ---------------- launch ----------------
extern "C" void kernel_launch(void* const* d_in, const int* in_sizes, int n_in,
                              void* d_out, int out_size)
{
    const int*   sids   = (const int*)d_in[0];
    const int*   eids   = (const int*)d_in[1];
    const int*   mids   = (const int*)d_in[2];
    const int*   counts = (const int*)d_in[3];
    const float* embed  = (const float*)d_in[4];
    const float* W      = (const float*)d_in[5];
    const float* bnode  = (const float*)d_in[6];
    const float* W1     = (const float*)d_in[7];
    const float* b1     = (const float*)d_in[8];
    const float* W2     = (const float*)d_in[9];
    const float* b2     = (const float*)d_in[10];
    const float* W3     = (const float*)d_in[11];
    const float* b3     = (const float*)d_in[12];

    float *bufA, *bufB, *pooledT, *h1T, *h2T;
    int *meta;
    cudaGetSymbolAddress((void**)&bufA, g_bufA);
    cudaGetSymbolAddress((void**)&bufB, g_bufB);
    cudaGetSymbolAddress((void**)&pooledT, g_pooledT);
    cudaGetSymbolAddress((void**)&h1T, g_h1T);
    cudaGetSymbolAddress((void**)&h2T, g_h2T);
    cudaGetSymbolAddress((void**)&meta, g_meta);

    // metadata
    cudaMemsetAsync(meta, 0, LL * NNODE * sizeof(int));
    build_lists_kernel<<<(NPAIR * LL + 255) / 256, 256>>>(mids);

    const int lgrid = NNODE * 4;   // chunk slots; empty ones exit immediately
    layer_mma_kernel<true ><<<lgrid, 256>>>(0, W, bnode, sids, eids, embed, nullptr, bufA);
    layer_mma_kernel<false><<<lgrid, 256>>>(1, W, bnode, sids, eids, embed, bufA, bufB);
    layer_mma_kernel<false><<<lgrid, 256>>>(2, W, bnode, sids, eids, embed, bufB, bufA);
    layer_mma_kernel<false><<<lgrid, 256>>>(3, W, bnode, sids, eids, embed, bufA, bufB);

    pool_kernel<<<BB, 256>>>(bufB, counts, pooledT);
    mlp_kernel<2 * EE><<<C1 / 8, 256>>>(W1, b1, pooledT, h1T);
    mlp_kernel<C1>    <<<C2 / 8, 256>>>(W2, b2, h1T, h2T);
    out_kernel<<<1, 256>>>(W3, b3, h2T, (float*)d_out);
}

// round 15
// speedup vs baseline: 1.0034x; 1.0034x over previous
#include <cuda_runtime.h>
#include <cuda_bf16.h>
#include <cstdint>
#include <math.h>

// Problem constants (fixed by reference)
#define BB 256
#define PP 16
#define LL 4
#define EE 128
#define NPAIR 4096
#define NNODE 512
#define C1 512
#define C2 256
#define LIST_CAP 64
#define XSTRH 136            // X row stride in bf16 units (272B) -> conflict-free B frags
#define TGRID 256            // fused tail grid (all co-resident: 256 < 148*2)

typedef unsigned long long ull;
typedef unsigned short ushort_t;

// ---------------- device scratch (no allocations allowed) ----------------
__device__ float g_bufA[NPAIR * 2 * EE];   // 4 MB ping
__device__ float g_bufB[NPAIR * 2 * EE];   // 4 MB pong
__device__ float g_pooledT[2 * EE * BB];
__device__ float g_h1T[C1 * BB];
__device__ float g_h2T[C2 * BB];
__device__ int   g_meta[LL * NNODE + 4];   // list counts + 3 sync counters (memset together)
__device__ int   g_list[LL * NNODE * LIST_CAP];

// ---------------- helpers ----------------
__device__ __forceinline__ void fma2(ull& d, ull a, ull b) {
    asm("fma.rn.f32x2 %0, %1, %2, %0;" : "+l"(d) : "l"(a), "l"(b));
}
__device__ __forceinline__ ull pack2(float x) {
    ull r; unsigned u = __float_as_uint(x);
    asm("mov.b64 %0, {%1, %2};" : "=l"(r) : "r"(u), "r"(u));
    return r;
}
__device__ __forceinline__ ull packab(float a, float b) {
    ull r;
    asm("mov.b64 %0, {%1, %2};" : "=l"(r) : "r"(__float_as_uint(a)), "r"(__float_as_uint(b)));
    return r;
}
// pack two floats into bf16x2 (x0 -> low half, x1 -> high half)
__device__ __forceinline__ uint32_t cvt_bf16x2(float x0, float x1) {
    uint32_t r;
    asm("cvt.rn.bf16x2.f32 %0, %1, %2;" : "=r"(r) : "f"(x1), "f"(x0));
    return r;
}
// given float2 (x0,x1): produce hi-pack and lo-pack (residual) bf16x2
__device__ __forceinline__ void split2(float x0, float x1, uint32_t& hi, uint32_t& lo) {
    hi = cvt_bf16x2(x0, x1);
    float h0 = __uint_as_float(hi << 16);
    float h1 = __uint_as_float(hi & 0xffff0000u);
    lo = cvt_bf16x2(x0 - h0, x1 - h1);
}
__device__ __forceinline__ void mma16816(float* c, uint32_t a0, uint32_t a1, uint32_t a2, uint32_t a3,
                                         uint32_t b0, uint32_t b1) {
    asm volatile(
        "mma.sync.aligned.m16n8k16.row.col.f32.bf16.bf16.f32 "
        "{%0,%1,%2,%3}, {%4,%5,%6,%7}, {%8,%9}, {%0,%1,%2,%3};"
        : "+f"(c[0]), "+f"(c[1]), "+f"(c[2]), "+f"(c[3])
        : "r"(a0), "r"(a1), "r"(a2), "r"(a3), "r"(b0), "r"(b1));
}
// grid-wide barrier (all TGRID blocks are co-resident by construction)
__device__ __forceinline__ void gridsync(int* c) {
    __syncthreads();
    if (threadIdx.x == 0) {
        __threadfence();
        atomicAdd(c, 1);
        while (atomicAdd(c, 0) < (int)gridDim.x) { }
    }
    __syncthreads();
}

// ---------------- list building ----------------
__global__ void build_lists_kernel(const int* __restrict__ mids)
{
    int idx = blockIdx.x * 256 + threadIdx.x;
    if (idx >= NPAIR * LL) return;
    int p = idx >> 2, l = idx & 3;
    int node = mids[p * LL + l];
    int pos = atomicAdd(&g_meta[l * NNODE + node], 1);
    if (pos < LIST_CAP)
        g_list[(l * NNODE + node) * LIST_CAP + pos] = p;
}

// ---------------- layer kernel: block = (node, chunk-slot, rowhalf) ----------------
// grid.x = NNODE*4*2; empty chunk slots exit. 128 threads = 4 warps.
// warp w computes rows rh*64 + [w*16, w*16+16) x 32 vectors.
// W loaded fp32 (fragment pattern) with next-k-step prefetch; split to bf16 hi/lo
// in registers; each W element read once per block, reused by all 3 split-products.
template <bool FIRST>
__global__ __launch_bounds__(128, 6) void layer_mma_kernel(
    int layer, const float* __restrict__ Wg, const float* __restrict__ bias,
    const int* __restrict__ sids, const int* __restrict__ eids,
    const float* __restrict__ embed,
    const float* __restrict__ bufIn, float* __restrict__ bufOut)
{
    const int rh   = blockIdx.x & 1;
    const int slot = blockIdx.x >> 1;
    const int node = slot >> 2;
    const int c0   = (slot & 3) << 4;
    int kp = g_meta[layer * NNODE + node];
    kp = kp < LIST_CAP ? kp : LIST_CAP;
    if (c0 >= kp) return;
    const int nv = 2 * min(16, kp - c0);
    const int* lst = &g_list[(layer * NNODE + node) * LIST_CAP + c0];

    __shared__ ushort_t sxh[32 * XSTRH];
    __shared__ ushort_t sxl[32 * XSTRH];

    const int tid = threadIdx.x, lane = tid & 31, w = tid >> 5;

    // ---- gather X, split into bf16 hi/lo tiles (vectors >= nv stale; discarded) ----
    for (int f = tid; f < nv * 32; f += 128) {
        int v = f >> 5, i4 = f & 31;
        int pr = lst[v >> 1];
        const float4* src;
        if (FIRST) {
            int id = (v & 1) ? eids[pr] : sids[pr];
            src = (const float4*)(embed + (size_t)id * EE);
        } else {
            src = (const float4*)(bufIn + ((size_t)pr * 2 + (v & 1)) * EE);
        }
        float4 x = src[i4];
        uint32_t h01, l01, h23, l23;
        split2(x.x, x.y, h01, l01);
        split2(x.z, x.w, h23, l23);
        int o = v * XSTRH + i4 * 4;
        *(uint2*)&sxh[o] = make_uint2(h01, h23);
        *(uint2*)&sxl[o] = make_uint2(l01, l23);
    }
    __syncthreads();

    // ---- 3-product bf16-split mma: Whi*Xhi + Whi*Xlo + Wlo*Xhi ----
    float c[4][4];
    #pragma unroll
    for (int nt = 0; nt < 4; ++nt)
        #pragma unroll
        for (int q = 0; q < 4; ++q) c[nt][q] = 0.f;

    const float* Wn = Wg + (size_t)node * EE * EE;
    const int rbase = rh * 64 + w * 16 + (lane >> 2);   // A frag row (q adds 8)
    const int kbase = (lane & 3) << 1;                  // A/B frag k pair base
    const int brow = lane >> 2;                         // B frag: n offset within ntile
    const float* wrow = Wn + (size_t)rbase * EE + kbase;

#define LOADW(dst, sp) { const float* _p = wrow + (sp) * 16;       \
        dst[0] = *(const float2*)_p;                               \
        dst[1] = *(const float2*)(_p + 8 * EE);                    \
        dst[2] = *(const float2*)(_p + 8);                         \
        dst[3] = *(const float2*)(_p + 8 * EE + 8); }

    float2 cw[4], nw[4];
    LOADW(cw, 0);
    #pragma unroll
    for (int s = 0; s < 8; ++s) {
        if (s < 7) LOADW(nw, s + 1);                    // prefetch next k-step
        uint32_t ahi[4], alo[4];
        split2(cw[0].x, cw[0].y, ahi[0], alo[0]);
        split2(cw[1].x, cw[1].y, ahi[1], alo[1]);
        split2(cw[2].x, cw[2].y, ahi[2], alo[2]);
        split2(cw[3].x, cw[3].y, ahi[3], alo[3]);
        #pragma unroll
        for (int nt = 0; nt < 4; ++nt) {
            const int xo = (nt * 8 + brow) * XSTRH + s * 16 + kbase;
            uint32_t bh0 = *(const uint32_t*)&sxh[xo];
            uint32_t bh1 = *(const uint32_t*)&sxh[xo + 8];
            uint32_t bl0 = *(const uint32_t*)&sxl[xo];
            uint32_t bl1 = *(const uint32_t*)&sxl[xo + 8];
            mma16816(c[nt], ahi[0], ahi[1], ahi[2], ahi[3], bh0, bh1);
            mma16816(c[nt], ahi[0], ahi[1], ahi[2], ahi[3], bl0, bl1);
            mma16816(c[nt], alo[0], alo[1], alo[2], alo[3], bh0, bh1);
        }
        #pragma unroll
        for (int q = 0; q < 4; ++q) cw[q] = nw[q];
    }
#undef LOADW

    // ---- epilogue: +bias, guarded scatter ----
    const int r0 = rbase;
    const float bv0 = bias[node * EE + r0];
    const float bv1 = bias[node * EE + r0 + 8];
    #pragma unroll
    for (int nt = 0; nt < 4; ++nt) {
        int v0 = nt * 8 + ((lane & 3) << 1);
        int v1 = v0 + 1;
        if (v0 < nv) {
            int pr = lst[v0 >> 1];
            float* dst = bufOut + ((size_t)pr * 2 + (v0 & 1)) * EE;
            dst[r0]     = c[nt][0] + bv0;
            dst[r0 + 8] = c[nt][2] + bv1;
        }
        if (v1 < nv) {
            int pr = lst[v1 >> 1];
            float* dst = bufOut + ((size_t)pr * 2 + (v1 & 1)) * EE;
            dst[r0]     = c[nt][1] + bv0;
            dst[r0 + 8] = c[nt][3] + bv1;
        }
    }
}

// ---------------- fused tail: pool + MLP1 + MLP2 + out in one kernel ----------------
// 256 blocks x 256 threads; all blocks co-resident -> atomic-counter grid sync is safe.
__global__ __launch_bounds__(256) void tail_kernel(
    const float* __restrict__ buf, const int* __restrict__ counts,
    const float* __restrict__ W1, const float* __restrict__ b1,
    const float* __restrict__ W2, const float* __restrict__ b2,
    const float* __restrict__ W3, const float* __restrict__ b3,
    float* __restrict__ out)
{
    __shared__ float wt[C1 * 8];       // 16 KB (max of both MLP tiles)
    const int t = threadIdx.x, blk = blockIdx.x;
    int* sync = &g_meta[LL * NNODE];

    // ---- phase 1: pool — block = batch b; thread = feature f ----
    {
        const int b = blk;
        const int half = t >> 7, fi = t & 127;
        float acc = 0.f, cs = 0.f;
        #pragma unroll
        for (int p = 0; p < PP; ++p) {
            float cc = (float)counts[b * PP + p];
            acc += cc * buf[((size_t)((b * PP + p) * 2 + half)) * EE + fi];
            cs += cc;
        }
        g_pooledT[(size_t)t * BB + b] = acc / cs;
    }
    gridsync(&sync[0]);

    // ---- phase 2: MLP1 (256 -> 512, relu) — block = (8 j's) x (64 batches) ----
    {
        const int jt = (blk >> 2) * 8;          // 64 j-groups
        const int tb = (blk & 3) * 64;          // 4 batch-groups
        for (int f = t; f < 256 * 8; f += 256) {
            int i = f >> 3, jj = f & 7;
            wt[f] = W1[(size_t)(jt + jj) * 256 + i];
        }
        __syncthreads();
        const int jj = t >> 5, tt = t & 31;     // output j = jt+jj, batches tb+tt, tb+tt+32
        ull acc = 0ull;
        #pragma unroll 8
        for (int i = 0; i < 256; ++i) {
            float x0 = g_pooledT[(size_t)i * BB + tb + tt];
            float x1 = g_pooledT[(size_t)i * BB + tb + tt + 32];
            fma2(acc, pack2(wt[i * 8 + jj]), packab(x0, x1));
        }
        float bv = b1[jt + jj];
        g_h1T[(size_t)(jt + jj) * BB + tb + tt]      = fmaxf(__uint_as_float((unsigned)acc) + bv, 0.f);
        g_h1T[(size_t)(jt + jj) * BB + tb + tt + 32] = fmaxf(__uint_as_float((unsigned)(acc >> 32)) + bv, 0.f);
    }
    gridsync(&sync[1]);

    // ---- phase 3: MLP2 (512 -> 256, relu) — 128 active blocks ----
    if (blk < 128) {
        const int jt = (blk >> 2) * 8;          // 32 j-groups
        const int tb = (blk & 3) * 64;
        for (int f = t; f < 512 * 8; f += 256) {
            int i = f >> 3, jj = f & 7;
            wt[f] = W2[(size_t)(jt + jj) * 512 + i];
        }
        __syncthreads();
        const int jj = t >> 5, tt = t & 31;
        ull acc = 0ull;
        #pragma unroll 8
        for (int i = 0; i < 512; ++i) {
            float x0 = g_h1T[(size_t)i * BB + tb + tt];
            float x1 = g_h1T[(size_t)i * BB + tb + tt + 32];
            fma2(acc, pack2(wt[i * 8 + jj]), packab(x0, x1));
        }
        float bv = b2[jt + jj];
        g_h2T[(size_t)(jt + jj) * BB + tb + tt]      = fmaxf(__uint_as_float((unsigned)acc) + bv, 0.f);
        g_h2T[(size_t)(jt + jj) * BB + tb + tt + 32] = fmaxf(__uint_as_float((unsigned)(acc >> 32)) + bv, 0.f);
    }
    gridsync(&sync[2]);

    // ---- phase 4: out — block 0 only ----
    if (blk == 0) {
        float acc = 0.f;
        #pragma unroll 8
        for (int j = 0; j < C2; ++j)
            acc += W3[j] * g_h2T[(size_t)j * BB + t];
        acc += b3[0];
        out[t] = 1.f / (1.f + expf(-acc));
    }
}

// ---------------- launch ----------------
extern "C" void kernel_launch(void* const* d_in, const int* in_sizes, int n_in,
                              void* d_out, int out_size)
{
    const int*   sids   = (const int*)d_in[0];
    const int*   eids   = (const int*)d_in[1];
    const int*   mids   = (const int*)d_in[2];
    const int*   counts = (const int*)d_in[3];
    const float* embed  = (const float*)d_in[4];
    const float* W      = (const float*)d_in[5];
    const float* bnode  = (const float*)d_in[6];
    const float* W1     = (const float*)d_in[7];
    const float* b1     = (const float*)d_in[8];
    const float* W2     = (const float*)d_in[9];
    const float* b2     = (const float*)d_in[10];
    const float* W3     = (const float*)d_in[11];
    const float* b3     = (const float*)d_in[12];

    float *bufA, *bufB;
    int *meta;
    cudaGetSymbolAddress((void**)&bufA, g_bufA);
    cudaGetSymbolAddress((void**)&bufB, g_bufB);
    cudaGetSymbolAddress((void**)&meta, g_meta);

    // zero list counters AND tail sync counters (deterministic per replay)
    cudaMemsetAsync(meta, 0, (LL * NNODE + 4) * sizeof(int));
    build_lists_kernel<<<(NPAIR * LL + 255) / 256, 256>>>(mids);

    const int lgrid = NNODE * 4 * 2;   // (node, chunk-slot, rowhalf); empty slots exit
    layer_mma_kernel<true ><<<lgrid, 128>>>(0, W, bnode, sids, eids, embed, nullptr, bufA);
    layer_mma_kernel<false><<<lgrid, 128>>>(1, W, bnode, sids, eids, embed, bufA, bufB);
    layer_mma_kernel<false><<<lgrid, 128>>>(2, W, bnode, sids, eids, embed, bufB, bufA);
    layer_mma_kernel<false><<<lgrid, 128>>>(3, W, bnode, sids, eids, embed, bufA, bufB);

    tail_kernel<<<TGRID, 256>>>(bufB, counts, W1, b1, W2, b2, W3, b3, (float*)d_out);
}